// round 14
// baseline (speedup 1.0000x reference)
#include <cuda_runtime.h>
#include <cuda_fp16.h>
#include <cstdint>

// ============================================================================
// C[8192,1024] = A[8192,4096] @ B[1024,4096]^T   (fp32 in/out)
//
// Base sm_103 (no tcgen05). fp16 mma.sync.m16n8k16 (rel_err 2.9e-4).
// R12: single HYBRID kernel -- converter blocks (low bids, guaranteed
// wave-1 residency) produce fp16 A k-panels in order; GEMM CTAs (R7
// champion) acquire-poll panel flags before stage loads. Deadlock-free
// by bid-order dispatch; no streams, no events, no GEMM-side fences.
// ============================================================================

static constexpr int M_TOTAL = 8192;
static constexpr int K_DIM   = 4096;
static constexpr int N_TOTAL = 1024;

static constexpr int BM = 128;
static constexpr int BN = 128;
static constexpr int BK = 64;
static constexpr int STAGES = 3;
static constexpr int NK = K_DIM / BK;  // 64 panels

static constexpr int TILE_BYTES  = BM * BK * 2;          // 16384
static constexpr int STAGE_BYTES = 2 * TILE_BYTES;       // 32768
static constexpr int SMEM_TOTAL  = STAGES * STAGE_BYTES; // 98304 -> 2 blocks/SM

static constexpr int CVT_BLOCKS  = 128;                  // A converter blocks
static constexpr int GEMM_BLOCKS = (M_TOTAL / BM) * (N_TOTAL / BN);  // 512
static constexpr int GRID_TOTAL  = CVT_BLOCKS + GEMM_BLOCKS;         // 640
static constexpr int ROWS_PER_CVT = M_TOTAL / CVT_BLOCKS;            // 64

static constexpr int NB4 = (N_TOTAL * K_DIM) / 4;

// --------------------------------------------------------------------------
// Static scratch
// --------------------------------------------------------------------------
__device__ __half g_Ah[(size_t)M_TOTAL * K_DIM];
__device__ __half g_Bh[(size_t)N_TOTAL * K_DIM];
__device__ int    g_flag[NK];     // flag[p]==CVT_BLOCKS -> panel p ready

// --------------------------------------------------------------------------
// Head kernel: zero flags + convert B
// --------------------------------------------------------------------------
__device__ __forceinline__ uint2 cvt4(float4 v) {
    __half2 lo = __floats2half2_rn(v.x, v.y);
    __half2 hi = __floats2half2_rn(v.z, v.w);
    return make_uint2(*reinterpret_cast<uint32_t*>(&lo), *reinterpret_cast<uint32_t*>(&hi));
}

__global__ void __launch_bounds__(256)
head_kernel(const float4* __restrict__ B, uint2* __restrict__ Bh) {
    int i = blockIdx.x * blockDim.x + threadIdx.x;
    if (i < NK) g_flag[i] = 0;
    if (i < NB4) Bh[i] = cvt4(B[i]);
}

// --------------------------------------------------------------------------
// PTX helpers
// --------------------------------------------------------------------------
__device__ __forceinline__ void cp_async16(uint32_t saddr, const void* gptr) {
    asm volatile("cp.async.cg.shared.global [%0], [%1], 16;"
                 :: "r"(saddr), "l"(__cvta_generic_to_global(gptr)) : "memory");
}

#define CP_COMMIT() asm volatile("cp.async.commit_group;" ::: "memory")
#define CP_WAIT(N)  asm volatile("cp.async.wait_group %0;" :: "n"(N) : "memory")

#define LDSM_X4(R, addr)                                                     \
    asm volatile("ldmatrix.sync.aligned.m8n8.x4.shared.b16 {%0,%1,%2,%3}, [%4];" \
                 : "=r"((R)[0]), "=r"((R)[1]), "=r"((R)[2]), "=r"((R)[3])    \
                 : "r"(addr))

#define MMA_F16(C, A, B0, B1)                                                \
    asm volatile("mma.sync.aligned.m16n8k16.row.col.f32.f16.f16.f32 "        \
                 "{%0,%1,%2,%3}, {%4,%5,%6,%7}, {%8,%9}, {%0,%1,%2,%3};"     \
                 : "+f"((C)[0]), "+f"((C)[1]), "+f"((C)[2]), "+f"((C)[3])    \
                 : "r"((A)[0]), "r"((A)[1]), "r"((A)[2]), "r"((A)[3]),       \
                   "r"(B0), "r"(B1))

__device__ __forceinline__ uint32_t swz(int row, int col_bytes) {
    return (uint32_t)(row * 128 + (col_bytes ^ ((row & 7) * 16)));
}

__device__ __forceinline__ void wait_panel(int p) {
    const int* f = &g_flag[p];
    int v;
    for (;;) {
        asm volatile("ld.acquire.gpu.global.s32 %0, [%1];" : "=r"(v) : "l"(f));
        if (v >= CVT_BLOCKS) return;
        __nanosleep(128);
    }
}

// --------------------------------------------------------------------------
// Hybrid kernel: bids 0..255 even = converter, rest = GEMM (R7 champion)
// --------------------------------------------------------------------------
__global__ void __launch_bounds__(256, 2)
hybrid_kernel(const float* __restrict__ A32, float* __restrict__ C) {
    const int bid = blockIdx.x;
    const int tid = threadIdx.x;

    // ======================= CONVERTER ROLE =======================
    if (bid < 2 * CVT_BLOCKS && (bid & 1) == 0) {
        const int c  = bid >> 1;                 // 0..127
        const int r  = tid >> 2;                 // row within 64-row strip
        const int c4 = (tid & 3) * 4;            // 4 float4 per thread per row
        const size_t row4 = (size_t)(c * ROWS_PER_CVT + r) * (K_DIM / 4);
        const float4* A4 = reinterpret_cast<const float4*>(A32);
        uint2* Ah4 = reinterpret_cast<uint2*>(g_Ah);

        for (int p = 0; p < NK; p++) {
            const size_t i0 = row4 + p * 16 + c4;
            #pragma unroll
            for (int j = 0; j < 4; j++)
                Ah4[i0 + j] = cvt4(A4[i0 + j]);
            __threadfence();                     // publish at GPU scope
            __syncthreads();                     // whole block done with panel p
            if (tid == 0) {
                int* f = &g_flag[p];
                asm volatile("red.release.gpu.global.add.s32 [%0], 1;"
                             :: "l"(f) : "memory");
            }
        }
        return;
    }

    // ========================== GEMM ROLE ==========================
    const int g = (bid < 2 * CVT_BLOCKS) ? (bid >> 1) : (bid - CVT_BLOCKS);

    extern __shared__ uint8_t smem[];
    const uint32_t sbase = (uint32_t)__cvta_generic_to_shared(smem);

    const int lane = tid & 31;
    const int wid  = tid >> 5;
    const int wm   = (wid & 3) * 32;
    const int wn   = (wid >> 2) * 64;

    const int m0 = (g >> 3) * BM;    // octet shares A in L2
    const int n0 = (g & 7) * BN;

    auto load_stage = [&](int s, int kt) {
        const uint32_t st = sbase + s * STAGE_BYTES;
        const int kbase = kt * BK;
        #pragma unroll
        for (int i = 0; i < 4; i++) {
            const int idx = tid + i * 256;
            const int row = idx >> 3;
            const int ch  = idx & 7;
            const uint32_t soff = swz(row, ch * 16);
            cp_async16(st +              soff, &g_Ah[(size_t)(m0 + row) * K_DIM + kbase + ch * 8]);
            cp_async16(st + TILE_BYTES + soff, &g_Bh[(size_t)(n0 + row) * K_DIM + kbase + ch * 8]);
        }
    };

    int a_row[2], a_xor[2];
    #pragma unroll
    for (int m = 0; m < 2; m++) {
        const int r = wm + m * 16 + (lane & 15);
        a_row[m] = r * 128;
        a_xor[m] = (r & 7) * 16;
    }
    const int a_colb = (lane >> 4) * 16;
    int b_row[4], b_xor[4];
    #pragma unroll
    for (int p = 0; p < 4; p++) {
        const int r = wn + p * 16 + (lane & 7) + ((lane >> 4) << 3);
        b_row[p] = r * 128;
        b_xor[p] = (r & 7) * 16;
    }
    const int b_colb = ((lane >> 3) & 1) * 16;

    auto lds_frags = [&](uint32_t st, int ks, uint32_t (&a)[2][4], uint32_t (&b)[4][4]) {
        const int kb = ks * 32;
        #pragma unroll
        for (int m = 0; m < 2; m++)
            LDSM_X4(a[m], st + a_row[m] + ((kb + a_colb) ^ a_xor[m]));
        #pragma unroll
        for (int p = 0; p < 4; p++)
            LDSM_X4(b[p], st + TILE_BYTES + b_row[p] + ((kb + b_colb) ^ b_xor[p]));
    };

    float acc[2][8][4];
    #pragma unroll
    for (int m = 0; m < 2; m++)
        #pragma unroll
        for (int n = 0; n < 8; n++)
            #pragma unroll
            for (int q = 0; q < 4; q++) acc[m][n][q] = 0.f;

    // ---- prologue: gate stages on panel flags ----
    wait_panel(0);
    load_stage(0, 0); CP_COMMIT();
    wait_panel(1);
    load_stage(1, 1); CP_COMMIT();

    uint32_t af[2][2][4], bf[2][4][4];

    for (int kt = 0; kt < NK; kt++) {
        if (kt < NK - 1) { CP_WAIT(1); } else { CP_WAIT(0); }
        __syncthreads();
        if (kt + 2 < NK) {
            wait_panel(kt + 2);          // immediate-true after convert phase
            load_stage((kt + 2) % STAGES, kt + 2);
            CP_COMMIT();
        }

        const uint32_t st = sbase + (kt % STAGES) * STAGE_BYTES;

        lds_frags(st, 0, af[0], bf[0]);
        #pragma unroll
        for (int ks = 0; ks < 4; ks++) {
            const int cur = ks & 1;
            if (ks < 3)
                lds_frags(st, ks + 1, af[cur ^ 1], bf[cur ^ 1]);
            #pragma unroll
            for (int m = 0; m < 2; m++)
                #pragma unroll
                for (int p = 0; p < 4; p++)
                    #pragma unroll
                    for (int q = 0; q < 2; q++)
                        MMA_F16(acc[m][2 * p + q], af[cur][m],
                                bf[cur][p][2 * q], bf[cur][p][2 * q + 1]);
        }
    }

    // ---- epilogue: direct STG.64 ----
    #pragma unroll
    for (int m = 0; m < 2; m++) {
        const int r0 = m0 + wm + m * 16 + (lane >> 2);
        #pragma unroll
        for (int n = 0; n < 8; n++) {
            const int col = n0 + wn + n * 8 + (lane & 3) * 2;
            float2* q0 = reinterpret_cast<float2*>(&C[(size_t)r0 * N_TOTAL + col]);
            float2* q1 = reinterpret_cast<float2*>(&C[(size_t)(r0 + 8) * N_TOTAL + col]);
            *q0 = make_float2(acc[m][n][0], acc[m][n][1]);
            *q1 = make_float2(acc[m][n][2], acc[m][n][3]);
        }
    }
}

// --------------------------------------------------------------------------
// Launch: head (flags + B) -> hybrid (converters + GEMM in one grid)
// --------------------------------------------------------------------------
extern "C" void kernel_launch(void* const* d_in, const int* in_sizes, int n_in,
                              void* d_out, int out_size) {
    const float* A = (const float*)d_in[0];   // [8192, 4096]
    const float* B = (const float*)d_in[1];   // [1024, 4096]
    float* C = (float*)d_out;                 // [8192, 1024]

    __half* bH;
    cudaGetSymbolAddress((void**)&bH, g_Bh);

    static bool attr_set = false;
    if (!attr_set) {
        cudaFuncSetAttribute(hybrid_kernel,
                             cudaFuncAttributeMaxDynamicSharedMemorySize, SMEM_TOTAL);
        attr_set = true;
    }

    head_kernel<<<(NB4 + 255) / 256, 256>>>((const float4*)B, (uint2*)bH);
    hybrid_kernel<<<GRID_TOTAL, 256, SMEM_TOTAL>>>(A, C);
}

// round 15
// speedup vs baseline: 1.4726x; 1.4726x over previous
#include <cuda_runtime.h>
#include <cuda_fp16.h>
#include <cstdint>

// ============================================================================
// C[8192,1024] = A[8192,4096] @ B[1024,4096]^T   (fp32 in/out)
//
// Base sm_103 (no tcgen05). fp16 mma.sync.m16n8k16 (rel_err 2.9e-4).
// R13: R7 pipeline + R4's 64x64 warp tile: 128 threads/CTA (4 warps),
// LDSM/MMA = 8/32, cross-ks fragment double-buffering, 2 CTAs/SM.
// Overlap schemes abandoned (R5/R8-R12 all <= neutral).
// ============================================================================

static constexpr int M_TOTAL = 8192;
static constexpr int K_DIM   = 4096;
static constexpr int N_TOTAL = 1024;

static constexpr int BM = 128;
static constexpr int BN = 128;
static constexpr int BK = 64;          // 64 fp16 = 128 B per smem row
static constexpr int STAGES = 3;
static constexpr int NK = K_DIM / BK;  // 64

static constexpr int TILE_BYTES  = BM * BK * 2;          // 16384
static constexpr int STAGE_BYTES = 2 * TILE_BYTES;       // 32768
static constexpr int SMEM_TOTAL  = STAGES * STAGE_BYTES; // 98304 -> 2 CTAs/SM

// --------------------------------------------------------------------------
// Static scratch: fp16 copies of A and B
// --------------------------------------------------------------------------
__device__ __half g_Ah[(size_t)M_TOTAL * K_DIM];
__device__ __half g_Bh[(size_t)N_TOTAL * K_DIM];

static constexpr int NA4 = (M_TOTAL * K_DIM) / 4;   // 8388608
static constexpr int NB4 = (N_TOTAL * K_DIM) / 4;   // 1048576

// --------------------------------------------------------------------------
// Merged convert kernel (proven R7): A then B, fp32 -> fp16, 4-wide
// --------------------------------------------------------------------------
__global__ void __launch_bounds__(256)
cvt_all_kernel(const float4* __restrict__ A, const float4* __restrict__ B,
               uint2* __restrict__ Ah, uint2* __restrict__ Bh) {
    int i = blockIdx.x * blockDim.x + threadIdx.x;
    const float4* src;
    uint2* dst;
    if (i < NA4) {
        src = A + i; dst = Ah + i;
    } else {
        i -= NA4;
        if (i >= NB4) return;
        src = B + i; dst = Bh + i;
    }
    float4 v = *src;
    __half2 lo = __floats2half2_rn(v.x, v.y);
    __half2 hi = __floats2half2_rn(v.z, v.w);
    *dst = make_uint2(*reinterpret_cast<uint32_t*>(&lo), *reinterpret_cast<uint32_t*>(&hi));
}

// --------------------------------------------------------------------------
// PTX helpers
// --------------------------------------------------------------------------
__device__ __forceinline__ void cp_async16(uint32_t saddr, const void* gptr) {
    asm volatile("cp.async.cg.shared.global [%0], [%1], 16;"
                 :: "r"(saddr), "l"(__cvta_generic_to_global(gptr)) : "memory");
}

#define CP_COMMIT() asm volatile("cp.async.commit_group;" ::: "memory")
#define CP_WAIT(N)  asm volatile("cp.async.wait_group %0;" :: "n"(N) : "memory")

#define LDSM_X4(R, addr)                                                     \
    asm volatile("ldmatrix.sync.aligned.m8n8.x4.shared.b16 {%0,%1,%2,%3}, [%4];" \
                 : "=r"((R)[0]), "=r"((R)[1]), "=r"((R)[2]), "=r"((R)[3])    \
                 : "r"(addr))

#define MMA_F16(C, A, B0, B1)                                                \
    asm volatile("mma.sync.aligned.m16n8k16.row.col.f32.f16.f16.f32 "        \
                 "{%0,%1,%2,%3}, {%4,%5,%6,%7}, {%8,%9}, {%0,%1,%2,%3};"     \
                 : "+f"((C)[0]), "+f"((C)[1]), "+f"((C)[2]), "+f"((C)[3])    \
                 : "r"((A)[0]), "r"((A)[1]), "r"((A)[2]), "r"((A)[3]),       \
                   "r"(B0), "r"(B1))

__device__ __forceinline__ uint32_t swz(int row, int col_bytes) {
    return (uint32_t)(row * 128 + (col_bytes ^ ((row & 7) * 16)));
}

// --------------------------------------------------------------------------
// GEMM: CTA 128x128x64, 4 warps of 64x64, 3-stage cp.async, 2 CTAs/SM,
// cross-ks double-buffered fragments.
// --------------------------------------------------------------------------
__global__ void __launch_bounds__(128, 2)
gemm_f16_kernel(float* __restrict__ C) {
    extern __shared__ uint8_t smem[];
    const uint32_t sbase = (uint32_t)__cvta_generic_to_shared(smem);

    const int tid  = threadIdx.x;
    const int lane = tid & 31;
    const int wid  = tid >> 5;          // 0..3
    const int wm   = (wid & 1) * 64;
    const int wn   = (wid >> 1) * 64;

    const int m0 = (blockIdx.x >> 3) * BM;   // n-fastest: octet shares A in L2
    const int n0 = (blockIdx.x & 7) * BN;

    // ---- stage loader: 1024 x 16B chunks per array, 128 threads x 8 ----
    auto load_stage = [&](int s, int kt) {
        const uint32_t st = sbase + s * STAGE_BYTES;
        const int kbase = kt * BK;
        #pragma unroll
        for (int i = 0; i < 8; i++) {
            const int idx = tid + i * 128;
            const int row = idx >> 3;
            const int ch  = idx & 7;
            const uint32_t soff = swz(row, ch * 16);
            cp_async16(st +              soff, &g_Ah[(size_t)(m0 + row) * K_DIM + kbase + ch * 8]);
            cp_async16(st + TILE_BYTES + soff, &g_Bh[(size_t)(n0 + row) * K_DIM + kbase + ch * 8]);
        }
    };

    // ---- ldmatrix address components ----
    int a_row[4], a_xor[4];
    #pragma unroll
    for (int m = 0; m < 4; m++) {
        const int r = wm + m * 16 + (lane & 15);
        a_row[m] = r * 128;
        a_xor[m] = (r & 7) * 16;
    }
    const int a_colb = (lane >> 4) * 16;
    int b_row[4], b_xor[4];
    #pragma unroll
    for (int p = 0; p < 4; p++) {
        const int r = wn + p * 16 + (lane & 7) + ((lane >> 4) << 3);
        b_row[p] = r * 128;
        b_xor[p] = (r & 7) * 16;
    }
    const int b_colb = ((lane >> 3) & 1) * 16;

    auto lds_frags = [&](uint32_t st, int ks, uint32_t (&a)[4][4], uint32_t (&b)[4][4]) {
        const int kb = ks * 32;
        #pragma unroll
        for (int m = 0; m < 4; m++)
            LDSM_X4(a[m], st + a_row[m] + ((kb + a_colb) ^ a_xor[m]));
        #pragma unroll
        for (int p = 0; p < 4; p++)
            LDSM_X4(b[p], st + TILE_BYTES + b_row[p] + ((kb + b_colb) ^ b_xor[p]));
    };

    float acc[4][8][4];
    #pragma unroll
    for (int m = 0; m < 4; m++)
        #pragma unroll
        for (int n = 0; n < 8; n++)
            #pragma unroll
            for (int q = 0; q < 4; q++) acc[m][n][q] = 0.f;

    // ---- prologue: 2 stages in flight ----
    load_stage(0, 0); CP_COMMIT();
    load_stage(1, 1); CP_COMMIT();

    uint32_t af[2][4][4], bf[2][4][4];   // double-buffered fragments

    // ---- mainloop ----
    for (int kt = 0; kt < NK; kt++) {
        if (kt < NK - 1) { CP_WAIT(1); } else { CP_WAIT(0); }
        __syncthreads();   // stage kt ready; stage (kt+2)%3 consumed by all
        if (kt + 2 < NK) {
            load_stage((kt + 2) % STAGES, kt + 2);
            CP_COMMIT();
        }

        const uint32_t st = sbase + (kt % STAGES) * STAGE_BYTES;

        lds_frags(st, 0, af[0], bf[0]);            // preload ks=0
        #pragma unroll
        for (int ks = 0; ks < 4; ks++) {
            const int cur = ks & 1;
            if (ks < 3)
                lds_frags(st, ks + 1, af[cur ^ 1], bf[cur ^ 1]);  // prefetch next
            #pragma unroll
            for (int m = 0; m < 4; m++)
                #pragma unroll
                for (int p = 0; p < 4; p++)
                    #pragma unroll
                    for (int q = 0; q < 2; q++)
                        MMA_F16(acc[m][2 * p + q], af[cur][m],
                                bf[cur][p][2 * q], bf[cur][p][2 * q + 1]);
        }
    }

    // ---- epilogue: direct STG.64 ----
    #pragma unroll
    for (int m = 0; m < 4; m++) {
        const int r0 = m0 + wm + m * 16 + (lane >> 2);
        #pragma unroll
        for (int n = 0; n < 8; n++) {
            const int col = n0 + wn + n * 8 + (lane & 3) * 2;
            float2* q0 = reinterpret_cast<float2*>(&C[(size_t)r0 * N_TOTAL + col]);
            float2* q1 = reinterpret_cast<float2*>(&C[(size_t)(r0 + 8) * N_TOTAL + col]);
            *q0 = make_float2(acc[m][n][0], acc[m][n][1]);
            *q1 = make_float2(acc[m][n][2], acc[m][n][3]);
        }
    }
}

// --------------------------------------------------------------------------
// Launch
// --------------------------------------------------------------------------
extern "C" void kernel_launch(void* const* d_in, const int* in_sizes, int n_in,
                              void* d_out, int out_size) {
    const float* A = (const float*)d_in[0];   // [8192, 4096]
    const float* B = (const float*)d_in[1];   // [1024, 4096]
    float* C = (float*)d_out;                 // [8192, 1024]

    __half *aH, *bH;
    cudaGetSymbolAddress((void**)&aH, g_Ah);
    cudaGetSymbolAddress((void**)&bH, g_Bh);

    const int ncv = NA4 + NB4;
    cvt_all_kernel<<<(ncv + 255) / 256, 256>>>((const float4*)A, (const float4*)B,
                                               (uint2*)aH, (uint2*)bH);

    static bool attr_set = false;
    if (!attr_set) {
        cudaFuncSetAttribute(gemm_f16_kernel,
                             cudaFuncAttributeMaxDynamicSharedMemorySize, SMEM_TOTAL);
        attr_set = true;
    }
    const int grid = (M_TOTAL / BM) * (N_TOTAL / BN);   // 512
    gemm_f16_kernel<<<grid, 128, SMEM_TOTAL>>>(C);
}

// round 16
// speedup vs baseline: 1.6331x; 1.1090x over previous
#include <cuda_runtime.h>
#include <cuda_fp16.h>
#include <cstdint>

// ============================================================================
// C[8192,1024] = A[8192,4096] @ B[1024,4096]^T   (fp32 in/out)
//
// Base sm_103 (no tcgen05). fp16 mma.sync.m16n8k16 (rel_err 2.9e-4).
// R14: R13 champion (64x64 warp tile, 4 warps/CTA, 2 CTAs/SM, 3-stage
// cp.async, cross-ks fragment double-buffering) + per-kt critical-path fix:
// ks=0 LDSMs issue BEFORE the 16 stage-prefetch cp.asyncs, and stage
// offsets rotate in registers (no % in the loop).
// ============================================================================

static constexpr int M_TOTAL = 8192;
static constexpr int K_DIM   = 4096;
static constexpr int N_TOTAL = 1024;

static constexpr int BM = 128;
static constexpr int BN = 128;
static constexpr int BK = 64;          // 64 fp16 = 128 B per smem row
static constexpr int STAGES = 3;
static constexpr int NK = K_DIM / BK;  // 64

static constexpr int TILE_BYTES  = BM * BK * 2;          // 16384
static constexpr int STAGE_BYTES = 2 * TILE_BYTES;       // 32768
static constexpr int SMEM_TOTAL  = STAGES * STAGE_BYTES; // 98304 -> 2 CTAs/SM

// --------------------------------------------------------------------------
// Static scratch: fp16 copies of A and B
// --------------------------------------------------------------------------
__device__ __half g_Ah[(size_t)M_TOTAL * K_DIM];
__device__ __half g_Bh[(size_t)N_TOTAL * K_DIM];

static constexpr int NA4 = (M_TOTAL * K_DIM) / 4;   // 8388608
static constexpr int NB4 = (N_TOTAL * K_DIM) / 4;   // 1048576

// --------------------------------------------------------------------------
// Merged convert kernel: A then B, fp32 -> fp16, 4-wide (DRAM-roofline)
// --------------------------------------------------------------------------
__global__ void __launch_bounds__(256)
cvt_all_kernel(const float4* __restrict__ A, const float4* __restrict__ B,
               uint2* __restrict__ Ah, uint2* __restrict__ Bh) {
    int i = blockIdx.x * blockDim.x + threadIdx.x;
    const float4* src;
    uint2* dst;
    if (i < NA4) {
        src = A + i; dst = Ah + i;
    } else {
        i -= NA4;
        if (i >= NB4) return;
        src = B + i; dst = Bh + i;
    }
    float4 v = *src;
    __half2 lo = __floats2half2_rn(v.x, v.y);
    __half2 hi = __floats2half2_rn(v.z, v.w);
    *dst = make_uint2(*reinterpret_cast<uint32_t*>(&lo), *reinterpret_cast<uint32_t*>(&hi));
}

// --------------------------------------------------------------------------
// PTX helpers
// --------------------------------------------------------------------------
__device__ __forceinline__ void cp_async16(uint32_t saddr, const void* gptr) {
    asm volatile("cp.async.cg.shared.global [%0], [%1], 16;"
                 :: "r"(saddr), "l"(__cvta_generic_to_global(gptr)) : "memory");
}

#define CP_COMMIT() asm volatile("cp.async.commit_group;" ::: "memory")
#define CP_WAIT(N)  asm volatile("cp.async.wait_group %0;" :: "n"(N) : "memory")

#define LDSM_X4(R, addr)                                                     \
    asm volatile("ldmatrix.sync.aligned.m8n8.x4.shared.b16 {%0,%1,%2,%3}, [%4];" \
                 : "=r"((R)[0]), "=r"((R)[1]), "=r"((R)[2]), "=r"((R)[3])    \
                 : "r"(addr))

#define MMA_F16(C, A, B0, B1)                                                \
    asm volatile("mma.sync.aligned.m16n8k16.row.col.f32.f16.f16.f32 "        \
                 "{%0,%1,%2,%3}, {%4,%5,%6,%7}, {%8,%9}, {%0,%1,%2,%3};"     \
                 : "+f"((C)[0]), "+f"((C)[1]), "+f"((C)[2]), "+f"((C)[3])    \
                 : "r"((A)[0]), "r"((A)[1]), "r"((A)[2]), "r"((A)[3]),       \
                   "r"(B0), "r"(B1))

__device__ __forceinline__ uint32_t swz(int row, int col_bytes) {
    return (uint32_t)(row * 128 + (col_bytes ^ ((row & 7) * 16)));
}

// --------------------------------------------------------------------------
// GEMM: CTA 128x128x64, 4 warps of 64x64, 3-stage cp.async, 2 CTAs/SM.
// --------------------------------------------------------------------------
__global__ void __launch_bounds__(128, 2)
gemm_f16_kernel(float* __restrict__ C) {
    extern __shared__ uint8_t smem[];
    const uint32_t sbase = (uint32_t)__cvta_generic_to_shared(smem);

    const int tid  = threadIdx.x;
    const int lane = tid & 31;
    const int wid  = tid >> 5;          // 0..3
    const int wm   = (wid & 1) * 64;
    const int wn   = (wid >> 1) * 64;

    const int m0 = (blockIdx.x >> 3) * BM;   // n-fastest: octet shares A in L2
    const int n0 = (blockIdx.x & 7) * BN;

    // ---- stage loader: 1024 x 16B chunks per array, 128 threads x 8 ----
    auto load_stage = [&](uint32_t st, int kt) {
        const int kbase = kt * BK;
        #pragma unroll
        for (int i = 0; i < 8; i++) {
            const int idx = tid + i * 128;
            const int row = idx >> 3;
            const int ch  = idx & 7;
            const uint32_t soff = swz(row, ch * 16);
            cp_async16(st +              soff, &g_Ah[(size_t)(m0 + row) * K_DIM + kbase + ch * 8]);
            cp_async16(st + TILE_BYTES + soff, &g_Bh[(size_t)(n0 + row) * K_DIM + kbase + ch * 8]);
        }
    };

    // ---- ldmatrix address components ----
    int a_row[4], a_xor[4];
    #pragma unroll
    for (int m = 0; m < 4; m++) {
        const int r = wm + m * 16 + (lane & 15);
        a_row[m] = r * 128;
        a_xor[m] = (r & 7) * 16;
    }
    const int a_colb = (lane >> 4) * 16;
    int b_row[4], b_xor[4];
    #pragma unroll
    for (int p = 0; p < 4; p++) {
        const int r = wn + p * 16 + (lane & 7) + ((lane >> 4) << 3);
        b_row[p] = r * 128;
        b_xor[p] = (r & 7) * 16;
    }
    const int b_colb = ((lane >> 3) & 1) * 16;

    auto lds_frags = [&](uint32_t st, int ks, uint32_t (&a)[4][4], uint32_t (&b)[4][4]) {
        const int kb = ks * 32;
        #pragma unroll
        for (int m = 0; m < 4; m++)
            LDSM_X4(a[m], st + a_row[m] + ((kb + a_colb) ^ a_xor[m]));
        #pragma unroll
        for (int p = 0; p < 4; p++)
            LDSM_X4(b[p], st + TILE_BYTES + b_row[p] + ((kb + b_colb) ^ b_xor[p]));
    };

    float acc[4][8][4];
    #pragma unroll
    for (int m = 0; m < 4; m++)
        #pragma unroll
        for (int n = 0; n < 8; n++)
            #pragma unroll
            for (int q = 0; q < 4; q++) acc[m][n][q] = 0.f;

    // ---- prologue: 2 stages in flight ----
    load_stage(sbase + 0 * STAGE_BYTES, 0); CP_COMMIT();
    load_stage(sbase + 1 * STAGE_BYTES, 1); CP_COMMIT();

    uint32_t af[2][4][4], bf[2][4][4];   // double-buffered fragments

    // rotating stage offsets: st_cur = stage kt, st_nxt2 = stage kt+2
    uint32_t st_cur  = sbase;                       // (kt)   % 3
    uint32_t st_nxt2 = sbase + 2 * STAGE_BYTES;     // (kt+2) % 3
    const uint32_t st_hi = sbase + 2 * STAGE_BYTES;

    // ---- mainloop ----
    for (int kt = 0; kt < NK; kt++) {
        if (kt < NK - 1) { CP_WAIT(1); } else { CP_WAIT(0); }
        __syncthreads();   // stage kt ready; stage (kt+2)%3 consumed by all

        // critical path first: fragments feeding this kt's first MMAs
        lds_frags(st_cur, 0, af[0], bf[0]);

        // then the (slack-rich) prefetch of stage kt+2
        if (kt + 2 < NK) {
            load_stage(st_nxt2, kt + 2);
            CP_COMMIT();
        }

        #pragma unroll
        for (int ks = 0; ks < 4; ks++) {
            const int cur = ks & 1;
            if (ks < 3)
                lds_frags(st_cur, ks + 1, af[cur ^ 1], bf[cur ^ 1]);  // prefetch next
            #pragma unroll
            for (int m = 0; m < 4; m++)
                #pragma unroll
                for (int p = 0; p < 4; p++)
                    #pragma unroll
                    for (int q = 0; q < 2; q++)
                        MMA_F16(acc[m][2 * p + q], af[cur][m],
                                bf[cur][p][2 * q], bf[cur][p][2 * q + 1]);
        }

        // rotate stage offsets
        st_cur  = (st_cur  == st_hi) ? sbase : st_cur  + STAGE_BYTES;
        st_nxt2 = (st_nxt2 == st_hi) ? sbase : st_nxt2 + STAGE_BYTES;
    }

    // ---- epilogue: direct STG.64 ----
    #pragma unroll
    for (int m = 0; m < 4; m++) {
        const int r0 = m0 + wm + m * 16 + (lane >> 2);
        #pragma unroll
        for (int n = 0; n < 8; n++) {
            const int col = n0 + wn + n * 8 + (lane & 3) * 2;
            float2* q0 = reinterpret_cast<float2*>(&C[(size_t)r0 * N_TOTAL + col]);
            float2* q1 = reinterpret_cast<float2*>(&C[(size_t)(r0 + 8) * N_TOTAL + col]);
            *q0 = make_float2(acc[m][n][0], acc[m][n][1]);
            *q1 = make_float2(acc[m][n][2], acc[m][n][3]);
        }
    }
}

// --------------------------------------------------------------------------
// Launch
// --------------------------------------------------------------------------
extern "C" void kernel_launch(void* const* d_in, const int* in_sizes, int n_in,
                              void* d_out, int out_size) {
    const float* A = (const float*)d_in[0];   // [8192, 4096]
    const float* B = (const float*)d_in[1];   // [1024, 4096]
    float* C = (float*)d_out;                 // [8192, 1024]

    __half *aH, *bH;
    cudaGetSymbolAddress((void**)&aH, g_Ah);
    cudaGetSymbolAddress((void**)&bH, g_Bh);

    const int ncv = NA4 + NB4;
    cvt_all_kernel<<<(ncv + 255) / 256, 256>>>((const float4*)A, (const float4*)B,
                                               (uint2*)aH, (uint2*)bH);

    static bool attr_set = false;
    if (!attr_set) {
        cudaFuncSetAttribute(gemm_f16_kernel,
                             cudaFuncAttributeMaxDynamicSharedMemorySize, SMEM_TOTAL);
        attr_set = true;
    }
    const int grid = (M_TOTAL / BM) * (N_TOTAL / BN);   // 512
    gemm_f16_kernel<<<grid, 128, SMEM_TOTAL>>>(C);
}